// round 1
// baseline (speedup 1.0000x reference)
#include <cuda_runtime.h>
#include <cuda_bf16.h>
#include <cstdint>

#define BSZ 8192
#define DIM 768
#define BM 128
#define BN 128
#define BK 32
#define SA 48   // padded shared row stride in bf16 elems (96B, 16B-aligned)

// Scratch (static device allocations — no cudaMalloc allowed)
__device__ float g_rowsum[BSZ];
__device__ float g_colsum[BSZ];
__device__ float g_diag[BSZ];
__device__ __nv_bfloat16 g_vn[BSZ * DIM];
__device__ __nv_bfloat16 g_un[BSZ * DIM];

// ---------------------------------------------------------------------------
// Kernel 0: zero the cross-block accumulators (must run every launch — graph
// replays reuse the same device globals).
// ---------------------------------------------------------------------------
__global__ void zero_kernel() {
    int i = blockIdx.x * blockDim.x + threadIdx.x;
    if (i < BSZ) {
        g_rowsum[i] = 0.0f;
        g_colsum[i] = 0.0f;
    }
}

// ---------------------------------------------------------------------------
// Kernel 1: per-row norms of v and u, diag_i = <v_i,u_i>/(|v_i||u_i|) in exact
// fp32, and normalized bf16 copies for the tensor-core GEMM.
// ---------------------------------------------------------------------------
__global__ void normalize_kernel(const float* __restrict__ v,
                                 const float* __restrict__ u) {
    int row = blockIdx.x;
    const float* vr = v + (size_t)row * DIM;
    const float* ur = u + (size_t)row * DIM;

    float sv = 0.f, su = 0.f, dp = 0.f;
    for (int j = threadIdx.x; j < DIM; j += 256) {
        float a = vr[j], b = ur[j];
        sv += a * a;
        su += b * b;
        dp += a * b;
    }
    #pragma unroll
    for (int o = 16; o > 0; o >>= 1) {
        sv += __shfl_xor_sync(0xFFFFFFFFu, sv, o);
        su += __shfl_xor_sync(0xFFFFFFFFu, su, o);
        dp += __shfl_xor_sync(0xFFFFFFFFu, dp, o);
    }
    __shared__ float sh[3][8];
    int w = threadIdx.x >> 5, l = threadIdx.x & 31;
    if (l == 0) { sh[0][w] = sv; sh[1][w] = su; sh[2][w] = dp; }
    __syncthreads();
    if (threadIdx.x == 0) {
        float a = 0.f, b = 0.f, c = 0.f;
        #pragma unroll
        for (int i = 0; i < 8; i++) { a += sh[0][i]; b += sh[1][i]; c += sh[2][i]; }
        float nv = fmaxf(sqrtf(a), 1e-8f);
        float nu = fmaxf(sqrtf(b), 1e-8f);
        g_diag[row] = c / (nv * nu);
        sh[0][0] = 1.0f / nv;
        sh[1][0] = 1.0f / nu;
    }
    __syncthreads();
    float iv = sh[0][0], iu = sh[1][0];
    for (int j = threadIdx.x; j < DIM; j += 256) {
        g_vn[(size_t)row * DIM + j] = __float2bfloat16(vr[j] * iv);
        g_un[(size_t)row * DIM + j] = __float2bfloat16(ur[j] * iu);
    }
}

// ---------------------------------------------------------------------------
// Kernel 2: bf16 tensor-core GEMM tile (128x128, K=768) with fused
// exp(logit - 10) and row/col partial-sum epilogue.
// Logit = cos/tau = cos*10, |cos| <= 1 so the fixed shift of 10 is safe:
// no online max needed, terms in (0, ~e^0.1].
// ---------------------------------------------------------------------------
__global__ __launch_bounds__(256, 2) void gemm_lse_kernel() {
    __shared__ __nv_bfloat16 As[BM * SA];
    __shared__ __nv_bfloat16 Bs[BN * SA];
    __shared__ float s_row[BM];
    __shared__ float s_col[BN];

    const int tid = threadIdx.x;
    const int m0 = blockIdx.y * BM;
    const int n0 = blockIdx.x * BN;

    if (tid < BM) s_row[tid] = 0.0f;
    if (tid < BN) s_col[tid] = 0.0f;

    const int warp = tid >> 5, lane = tid & 31;
    const int wm = warp >> 2;     // 0..1  (64-row slab)
    const int wn = warp & 3;      // 0..3  (32-col slab)
    const int gID = lane >> 2;    // 0..7
    const int tid4 = lane & 3;    // 0..3

    float acc[4][4][4];
    #pragma unroll
    for (int mt = 0; mt < 4; mt++)
        #pragma unroll
        for (int nt = 0; nt < 4; nt++)
            #pragma unroll
            for (int i = 0; i < 4; i++) acc[mt][nt][i] = 0.0f;

    for (int kt = 0; kt < DIM; kt += BK) {
        __syncthreads();
        // Cooperative load: 128 rows x 32 k of A and B (bf16), uint4 granules.
        #pragma unroll
        for (int it = 0; it < 2; it++) {
            int idx = tid + it * 256;       // 0..511
            int r = idx >> 2, g = idx & 3;  // row, 8-elem granule
            uint4 va = *(const uint4*)&g_vn[(size_t)(m0 + r) * DIM + kt + g * 8];
            *(uint4*)&As[r * SA + g * 8] = va;
            uint4 vb = *(const uint4*)&g_un[(size_t)(n0 + r) * DIM + kt + g * 8];
            *(uint4*)&Bs[r * SA + g * 8] = vb;
        }
        __syncthreads();

        #pragma unroll
        for (int kk = 0; kk < BK; kk += 16) {
            uint32_t af[4][4];
            #pragma unroll
            for (int mt = 0; mt < 4; mt++) {
                int r = wm * 64 + mt * 16 + gID;
                int c = kk + tid4 * 2;
                af[mt][0] = *(const uint32_t*)&As[r * SA + c];
                af[mt][1] = *(const uint32_t*)&As[(r + 8) * SA + c];
                af[mt][2] = *(const uint32_t*)&As[r * SA + c + 8];
                af[mt][3] = *(const uint32_t*)&As[(r + 8) * SA + c + 8];
            }
            uint32_t bfr[4][2];
            #pragma unroll
            for (int nt = 0; nt < 4; nt++) {
                int r = wn * 32 + nt * 8 + gID;
                int c = kk + tid4 * 2;
                bfr[nt][0] = *(const uint32_t*)&Bs[r * SA + c];
                bfr[nt][1] = *(const uint32_t*)&Bs[r * SA + c + 8];
            }
            #pragma unroll
            for (int mt = 0; mt < 4; mt++)
                #pragma unroll
                for (int nt = 0; nt < 4; nt++)
                    asm volatile(
                        "mma.sync.aligned.m16n8k16.row.col.f32.bf16.bf16.f32 "
                        "{%0,%1,%2,%3}, {%4,%5,%6,%7}, {%8,%9}, {%0,%1,%2,%3};"
                        : "+f"(acc[mt][nt][0]), "+f"(acc[mt][nt][1]),
                          "+f"(acc[mt][nt][2]), "+f"(acc[mt][nt][3])
                        : "r"(af[mt][0]), "r"(af[mt][1]),
                          "r"(af[mt][2]), "r"(af[mt][3]),
                          "r"(bfr[nt][0]), "r"(bfr[nt][1]));
        }
    }

    // Epilogue: e = exp(cos*10 - 10); accumulate per-row / per-col sums.
    float rs0[4] = {0.f, 0.f, 0.f, 0.f};   // rows gID     per mtile
    float rs1[4] = {0.f, 0.f, 0.f, 0.f};   // rows gID+8   per mtile
    float ce[4]  = {0.f, 0.f, 0.f, 0.f};   // cols tid4*2  per ntile
    float co[4]  = {0.f, 0.f, 0.f, 0.f};   // cols tid4*2+1
    #pragma unroll
    for (int mt = 0; mt < 4; mt++) {
        #pragma unroll
        for (int nt = 0; nt < 4; nt++) {
            float e0 = __expf(fmaf(acc[mt][nt][0], 10.0f, -10.0f));
            float e1 = __expf(fmaf(acc[mt][nt][1], 10.0f, -10.0f));
            float e2 = __expf(fmaf(acc[mt][nt][2], 10.0f, -10.0f));
            float e3 = __expf(fmaf(acc[mt][nt][3], 10.0f, -10.0f));
            rs0[mt] += e0 + e1;
            rs1[mt] += e2 + e3;
            ce[nt]  += e0 + e2;
            co[nt]  += e1 + e3;
        }
    }
    // Row sums: reduce across the 4 lanes sharing gID.
    #pragma unroll
    for (int mt = 0; mt < 4; mt++) {
        float v0 = rs0[mt], v1 = rs1[mt];
        v0 += __shfl_xor_sync(0xFFFFFFFFu, v0, 1);
        v0 += __shfl_xor_sync(0xFFFFFFFFu, v0, 2);
        v1 += __shfl_xor_sync(0xFFFFFFFFu, v1, 1);
        v1 += __shfl_xor_sync(0xFFFFFFFFu, v1, 2);
        if (tid4 == 0) {
            atomicAdd(&s_row[wm * 64 + mt * 16 + gID], v0);
            atomicAdd(&s_row[wm * 64 + mt * 16 + gID + 8], v1);
        }
    }
    // Col sums: reduce across the 8 lanes sharing tid4.
    #pragma unroll
    for (int nt = 0; nt < 4; nt++) {
        float a = ce[nt], b = co[nt];
        a += __shfl_xor_sync(0xFFFFFFFFu, a, 4);
        a += __shfl_xor_sync(0xFFFFFFFFu, a, 8);
        a += __shfl_xor_sync(0xFFFFFFFFu, a, 16);
        b += __shfl_xor_sync(0xFFFFFFFFu, b, 4);
        b += __shfl_xor_sync(0xFFFFFFFFu, b, 8);
        b += __shfl_xor_sync(0xFFFFFFFFu, b, 16);
        if (lane < 4) {
            atomicAdd(&s_col[wn * 32 + nt * 8 + lane * 2], a);
            atomicAdd(&s_col[wn * 32 + nt * 8 + lane * 2 + 1], b);
        }
    }
    __syncthreads();
    if (tid < 128)       atomicAdd(&g_rowsum[m0 + tid], s_row[tid]);
    else                 atomicAdd(&g_colsum[n0 + tid - 128], s_col[tid - 128]);
}

// ---------------------------------------------------------------------------
// Kernel 3: loss_i = lam*(log(rowsum)+10 - 10*diag) + (1-lam)*(log(colsum)+10
//           - 10*diag); out = mean.
// ---------------------------------------------------------------------------
__global__ void finalize_kernel(float* __restrict__ out) {
    float s = 0.0f;
    for (int i = threadIdx.x; i < BSZ; i += 256) {
        float d10 = g_diag[i] * 10.0f;
        float li = logf(g_rowsum[i]) + 10.0f - d10;
        float lt = logf(g_colsum[i]) + 10.0f - d10;
        s += 0.75f * li + 0.25f * lt;
    }
    #pragma unroll
    for (int o = 16; o > 0; o >>= 1) s += __shfl_xor_sync(0xFFFFFFFFu, s, o);
    __shared__ float sh[8];
    int w = threadIdx.x >> 5, l = threadIdx.x & 31;
    if (l == 0) sh[w] = s;
    __syncthreads();
    if (threadIdx.x == 0) {
        float t = 0.f;
        #pragma unroll
        for (int i = 0; i < 8; i++) t += sh[i];
        out[0] = t * (1.0f / BSZ);
    }
}

extern "C" void kernel_launch(void* const* d_in, const int* in_sizes, int n_in,
                              void* d_out, int out_size) {
    const float* v = (const float*)d_in[0];
    const float* u = (const float*)d_in[1];
    float* out = (float*)d_out;

    zero_kernel<<<(BSZ + 255) / 256, 256>>>();
    normalize_kernel<<<BSZ, 256>>>(v, u);
    dim3 grid(BSZ / BN, BSZ / BM);
    gemm_lse_kernel<<<grid, 256>>>();
    finalize_kernel<<<1, 256>>>(out);
}

// round 3
// speedup vs baseline: 1.8109x; 1.8109x over previous
#include <cuda_runtime.h>
#include <cuda_bf16.h>
#include <cstdint>

#define BSZ 8192
#define DIM 768
#define BK 64                       // K elems per pipeline stage
#define NCH (DIM / BK)              // 12
#define SROW 144                    // padded smem row stride in bytes (72 bf16)
#define TILE_B (128 * SROW)         // 18432 bytes per tile
#define OFF_A 0
#define OFF_B (2 * TILE_B)
#define SMEM_TOTAL (4 * TILE_B)     // 73728 bytes

// Static device scratch (no cudaMalloc allowed)
__device__ __align__(16) float g_rowsum[BSZ];
__device__ __align__(16) float g_colsum[BSZ];
__device__ __align__(16) float g_diag[BSZ];
__device__ float g_part[32];
__device__ __align__(16) __nv_bfloat16 g_vn[BSZ * DIM];
__device__ __align__(16) __nv_bfloat16 g_un[BSZ * DIM];

__device__ __forceinline__ uint32_t smem_u32(const void* p) {
    uint32_t a;
    asm("{ .reg .u64 t; cvta.to.shared.u64 t, %1; cvt.u32.u64 %0, t; }" : "=r"(a) : "l"(p));
    return a;
}
__device__ __forceinline__ void cp_async16(uint32_t dst, const void* src) {
    asm volatile("cp.async.cg.shared.global [%0], [%1], 16;" :: "r"(dst), "l"(src) : "memory");
}
__device__ __forceinline__ void cp_commit() {
    asm volatile("cp.async.commit_group;" ::: "memory");
}
template <int N>
__device__ __forceinline__ void cp_wait() {
    asm volatile("cp.async.wait_group %0;" :: "n"(N) : "memory");
}
__device__ __forceinline__ void ldmx4(uint32_t* r, uint32_t addr) {
    asm volatile("ldmatrix.sync.aligned.m8n8.x4.shared.b16 {%0,%1,%2,%3}, [%4];"
                 : "=r"(r[0]), "=r"(r[1]), "=r"(r[2]), "=r"(r[3]) : "r"(addr));
}
__device__ __forceinline__ void mma16816(float* d, const uint32_t* a, uint32_t b0, uint32_t b1) {
    asm volatile(
        "mma.sync.aligned.m16n8k16.row.col.f32.bf16.bf16.f32 "
        "{%0,%1,%2,%3}, {%4,%5,%6,%7}, {%8,%9}, {%0,%1,%2,%3};"
        : "+f"(d[0]), "+f"(d[1]), "+f"(d[2]), "+f"(d[3])
        : "r"(a[0]), "r"(a[1]), "r"(a[2]), "r"(a[3]), "r"(b0), "r"(b1));
}

// ---------------------------------------------------------------------------
// Kernel 1: normalize rows of v,u -> bf16; exact fp32 diag; zero accumulators.
// ---------------------------------------------------------------------------
__global__ void normalize_kernel(const float* __restrict__ v,
                                 const float* __restrict__ u) {
    int row = blockIdx.x;
    if (threadIdx.x == 0) { g_rowsum[row] = 0.0f; g_colsum[row] = 0.0f; }
    const float4* vr = (const float4*)(v + (size_t)row * DIM);
    const float4* ur = (const float4*)(u + (size_t)row * DIM);

    float sv = 0.f, su = 0.f, dp = 0.f;
    float4 a4, b4;
    const bool act = threadIdx.x < DIM / 4;   // 192 active
    if (act) {
        a4 = vr[threadIdx.x];
        b4 = ur[threadIdx.x];
        sv = a4.x * a4.x + a4.y * a4.y + a4.z * a4.z + a4.w * a4.w;
        su = b4.x * b4.x + b4.y * b4.y + b4.z * b4.z + b4.w * b4.w;
        dp = a4.x * b4.x + a4.y * b4.y + a4.z * b4.z + a4.w * b4.w;
    }
    #pragma unroll
    for (int o = 16; o > 0; o >>= 1) {
        sv += __shfl_xor_sync(0xFFFFFFFFu, sv, o);
        su += __shfl_xor_sync(0xFFFFFFFFu, su, o);
        dp += __shfl_xor_sync(0xFFFFFFFFu, dp, o);
    }
    __shared__ float sh[3][8];
    int w = threadIdx.x >> 5, l = threadIdx.x & 31;
    if (l == 0) { sh[0][w] = sv; sh[1][w] = su; sh[2][w] = dp; }
    __syncthreads();
    if (threadIdx.x == 0) {
        float a = 0.f, b = 0.f, c = 0.f;
        #pragma unroll
        for (int i = 0; i < 8; i++) { a += sh[0][i]; b += sh[1][i]; c += sh[2][i]; }
        float nv = fmaxf(sqrtf(a), 1e-8f);
        float nu = fmaxf(sqrtf(b), 1e-8f);
        g_diag[row] = c / (nv * nu);
        sh[0][0] = 1.0f / nv;
        sh[1][0] = 1.0f / nu;
    }
    __syncthreads();
    float iv = sh[0][0], iu = sh[1][0];
    if (act) {
        __nv_bfloat162 p0 = {__float2bfloat16(a4.x * iv), __float2bfloat16(a4.y * iv)};
        __nv_bfloat162 p1 = {__float2bfloat16(a4.z * iv), __float2bfloat16(a4.w * iv)};
        __nv_bfloat162 q0 = {__float2bfloat16(b4.x * iu), __float2bfloat16(b4.y * iu)};
        __nv_bfloat162 q1 = {__float2bfloat16(b4.z * iu), __float2bfloat16(b4.w * iu)};
        uint2* dv = (uint2*)(g_vn + (size_t)row * DIM);
        uint2* du = (uint2*)(g_un + (size_t)row * DIM);
        dv[threadIdx.x] = make_uint2(*(uint32_t*)&p0, *(uint32_t*)&p1);
        du[threadIdx.x] = make_uint2(*(uint32_t*)&q0, *(uint32_t*)&q1);
    }
}

// ---------------------------------------------------------------------------
// Kernel 2: 128x128 tile bf16 mma.sync GEMM, K=768, cp.async double-buffered,
// ldmatrix fragment loads, fused exp(10*cos-10) + row/col sum epilogue.
// ---------------------------------------------------------------------------
__global__ __launch_bounds__(256, 2) void gemm_lse_kernel() {
    extern __shared__ char smem[];
    __shared__ float s_row[128];
    __shared__ float s_col[128];
    const uint32_t sb = smem_u32(smem);

    const int tid = threadIdx.x;
    const int warp = tid >> 5, lane = tid & 31;
    const int m0 = blockIdx.y * 128, n0 = blockIdx.x * 128;

    if (tid < 128) { s_row[tid] = 0.0f; s_col[tid] = 0.0f; }

    const int wm = warp >> 2;        // 0..1 (64-row slab)
    const int wn = warp & 3;         // 0..3 (32-col slab)
    const int gID = lane >> 2;       // 0..7
    const int tid4 = lane & 3;       // 0..3

    // cp.async thread mapping: 4 iterations x (1 A-chunk + 1 B-chunk)
    const int ldr = tid >> 3;        // 0..31 base row
    const int ldg = (tid & 7) * 16;  // 16B granule in 128B of K-data

    // ldmatrix per-lane offsets
    const int aRow = lane & 15, aSel = (lane >> 4) * 16;
    const int bRow = lane & 7,  bSel = (lane >> 3) * 16;

    float acc[4][4][4];
    #pragma unroll
    for (int mt = 0; mt < 4; mt++)
        #pragma unroll
        for (int nt = 0; nt < 4; nt++)
            #pragma unroll
            for (int i = 0; i < 4; i++) acc[mt][nt][i] = 0.0f;

    auto load_tile = [&](int c, int buf) {
        const uint32_t dA = sb + OFF_A + buf * TILE_B;
        const uint32_t dB = sb + OFF_B + buf * TILE_B;
        const size_t koff = (size_t)c * BK * 2;   // bytes along row
        #pragma unroll
        for (int p = 0; p < 4; p++) {
            const int row = ldr + p * 32;
            cp_async16(dA + row * SROW + ldg,
                       (const char*)g_vn + ((size_t)(m0 + row) * DIM) * 2 + koff + ldg);
            cp_async16(dB + row * SROW + ldg,
                       (const char*)g_un + ((size_t)(n0 + row) * DIM) * 2 + koff + ldg);
        }
        cp_commit();
    };

    load_tile(0, 0);

    for (int c = 0; c < NCH; c++) {
        const int buf = c & 1;
        if (c + 1 < NCH) {
            load_tile(c + 1, (c + 1) & 1);
            cp_wait<1>();
        } else {
            cp_wait<0>();
        }
        __syncthreads();

        const uint32_t bA = sb + OFF_A + buf * TILE_B;
        const uint32_t bB = sb + OFF_B + buf * TILE_B;
        #pragma unroll
        for (int kp = 0; kp < 2; kp++) {
            const int kk = kp * 32;
            uint32_t bfr[4][4];
            #pragma unroll
            for (int nt = 0; nt < 4; nt++)
                ldmx4(bfr[nt], bB + (wn * 32 + nt * 8 + bRow) * SROW + kk * 2 + bSel);
            #pragma unroll
            for (int ks = 0; ks < 2; ks++) {
                const int kc = kk + ks * 16;
                uint32_t af[4][4];
                #pragma unroll
                for (int mt = 0; mt < 4; mt++)
                    ldmx4(af[mt], bA + (wm * 64 + mt * 16 + aRow) * SROW + kc * 2 + aSel);
                #pragma unroll
                for (int mt = 0; mt < 4; mt++)
                    #pragma unroll
                    for (int nt = 0; nt < 4; nt++)
                        mma16816(acc[mt][nt], af[mt], bfr[nt][ks * 2], bfr[nt][ks * 2 + 1]);
            }
        }
        __syncthreads();
    }

    // Epilogue: e = exp(cos*10 - 10); per-row / per-col partial sums.
    float rs0[4] = {0.f, 0.f, 0.f, 0.f};
    float rs1[4] = {0.f, 0.f, 0.f, 0.f};
    float ce[4]  = {0.f, 0.f, 0.f, 0.f};
    float co[4]  = {0.f, 0.f, 0.f, 0.f};
    #pragma unroll
    for (int mt = 0; mt < 4; mt++) {
        #pragma unroll
        for (int nt = 0; nt < 4; nt++) {
            float e0 = __expf(fmaf(acc[mt][nt][0], 10.0f, -10.0f));
            float e1 = __expf(fmaf(acc[mt][nt][1], 10.0f, -10.0f));
            float e2 = __expf(fmaf(acc[mt][nt][2], 10.0f, -10.0f));
            float e3 = __expf(fmaf(acc[mt][nt][3], 10.0f, -10.0f));
            rs0[mt] += e0 + e1;
            rs1[mt] += e2 + e3;
            ce[nt]  += e0 + e2;
            co[nt]  += e1 + e3;
        }
    }
    #pragma unroll
    for (int mt = 0; mt < 4; mt++) {
        float v0 = rs0[mt], v1 = rs1[mt];
        v0 += __shfl_xor_sync(0xFFFFFFFFu, v0, 1);
        v0 += __shfl_xor_sync(0xFFFFFFFFu, v0, 2);
        v1 += __shfl_xor_sync(0xFFFFFFFFu, v1, 1);
        v1 += __shfl_xor_sync(0xFFFFFFFFu, v1, 2);
        if (tid4 == 0) {
            atomicAdd(&s_row[wm * 64 + mt * 16 + gID], v0);
            atomicAdd(&s_row[wm * 64 + mt * 16 + gID + 8], v1);
        }
    }
    #pragma unroll
    for (int nt = 0; nt < 4; nt++) {
        float a = ce[nt], b = co[nt];
        a += __shfl_xor_sync(0xFFFFFFFFu, a, 4);
        a += __shfl_xor_sync(0xFFFFFFFFu, a, 8);
        a += __shfl_xor_sync(0xFFFFFFFFu, a, 16);
        b += __shfl_xor_sync(0xFFFFFFFFu, b, 4);
        b += __shfl_xor_sync(0xFFFFFFFFu, b, 8);
        b += __shfl_xor_sync(0xFFFFFFFFu, b, 16);
        if (lane < 4) {
            atomicAdd(&s_col[wn * 32 + nt * 8 + lane * 2], a);
            atomicAdd(&s_col[wn * 32 + nt * 8 + lane * 2 + 1], b);
        }
    }
    __syncthreads();
    if (tid < 128)       atomicAdd(&g_rowsum[m0 + tid], s_row[tid]);
    else                 atomicAdd(&g_colsum[n0 + tid - 128], s_col[tid - 128]);
}

// ---------------------------------------------------------------------------
// Kernel 3a/3b: deterministic two-stage finalize.
// ---------------------------------------------------------------------------
__global__ void fin_a_kernel() {
    int i = blockIdx.x * 256 + threadIdx.x;
    float d10 = g_diag[i] * 10.0f;
    float li = logf(g_rowsum[i]) + 10.0f - d10;
    float lt = logf(g_colsum[i]) + 10.0f - d10;
    float s = 0.75f * li + 0.25f * lt;
    #pragma unroll
    for (int o = 16; o > 0; o >>= 1) s += __shfl_xor_sync(0xFFFFFFFFu, s, o);
    __shared__ float sh[8];
    int w = threadIdx.x >> 5, l = threadIdx.x & 31;
    if (l == 0) sh[w] = s;
    __syncthreads();
    if (threadIdx.x == 0) {
        float t = 0.f;
        #pragma unroll
        for (int i2 = 0; i2 < 8; i2++) t += sh[i2];
        g_part[blockIdx.x] = t;
    }
}
__global__ void fin_b_kernel(float* __restrict__ out) {
    float s = g_part[threadIdx.x];
    #pragma unroll
    for (int o = 16; o > 0; o >>= 1) s += __shfl_xor_sync(0xFFFFFFFFu, s, o);
    if (threadIdx.x == 0) out[0] = s * (1.0f / BSZ);
}

extern "C" void kernel_launch(void* const* d_in, const int* in_sizes, int n_in,
                              void* d_out, int out_size) {
    const float* v = (const float*)d_in[0];
    const float* u = (const float*)d_in[1];
    float* out = (float*)d_out;

    static bool attr_set = false;
    if (!attr_set) {
        cudaFuncSetAttribute(gemm_lse_kernel,
                             cudaFuncAttributeMaxDynamicSharedMemorySize, SMEM_TOTAL);
        attr_set = true;
    }

    normalize_kernel<<<BSZ, 256>>>(v, u);
    gemm_lse_kernel<<<dim3(64, 64), 256, SMEM_TOTAL>>>();
    fin_a_kernel<<<32, 256>>>();
    fin_b_kernel<<<1, 32>>>(out);
}